// round 7
// baseline (speedup 1.0000x reference)
#include <cuda_runtime.h>

#define NN   50000
#define NE   600000
#define LDIM 640
#define HID  128
#define SDIM 16
#define POUT 112
#define LN_EPS 1e-5f

// ---------------- scratch (no allocations allowed) ----------------
__device__ float g_x  [NN * HID];
__device__ float g_xws[NN * HID];   // xw * dis[row]  (pre-scaled)
__device__ float g_dis[NN];
__device__ int   g_cnt[NN];
__device__ int   g_off[NN];
__device__ int   g_cur[NN];
__device__ int   g_bkt[NE];
__device__ int   g_is64;            // 1 if index inputs are int64, 0 if int32

// ---------------- index access (dtype-agnostic) ----------------
// If the buffer is int64 (little-endian, values < 2^31), element i's low word
// sits at 32-bit position 2*i. If int32, it's at position i.
__device__ __forceinline__ int get_idx(const int* __restrict__ p, long i) {
    return g_is64 ? p[2 * i] : p[i];
}

// Detect layout: odd 32-bit words of an int64 array of small nonnegative
// values are all zero; for int32 random values in [0,NN) they are ~never all zero.
__global__ void detect_kernel(const int* __restrict__ ei32) {
    __shared__ int nz;
    if (threadIdx.x == 0) nz = 0;
    __syncthreads();
    int v = ei32[2 * threadIdx.x + 1];   // first 64 odd words
    if (v != 0) atomicAdd(&nz, 1);
    __syncthreads();
    if (threadIdx.x == 0) g_is64 = (nz == 0) ? 1 : 0;
}

// ---------------- f32x2 packed-FMA helpers ----------------
__device__ __forceinline__ unsigned long long pack_dup(float x) {
    unsigned long long r;
    asm("mov.b64 %0, {%1, %1};" : "=l"(r) : "f"(x));
    return r;
}
__device__ __forceinline__ void fma2(unsigned long long& d, unsigned long long a,
                                     unsigned long long b) {
    asm("fma.rn.f32x2 %0, %1, %2, %0;" : "+l"(d) : "l"(a), "l"(b));
}
__device__ __forceinline__ float2 unpack2(unsigned long long v) {
    float2 f;
    asm("mov.b64 {%0, %1}, %2;" : "=f"(f.x), "=f"(f.y) : "l"(v));
    return f;
}

// ---------------- degree / CSR build ----------------
__global__ void zero_cnt_kernel() {
    int i = blockIdx.x * 256 + threadIdx.x;
    if (i < NN) { g_cnt[i] = 0; g_cur[i] = 0; }
}

__global__ void count_deg_kernel(const int* __restrict__ ei) {
    int e = blockIdx.x * 256 + threadIdx.x;
    if (e >= NE) return;
    unsigned dst = (unsigned)get_idx(ei, (long)NE + e);
    if (dst < NN) atomicAdd(&g_cnt[dst], 1);
}

__global__ void dis_kernel() {
    int i = blockIdx.x * 256 + threadIdx.x;
    if (i < NN) g_dis[i] = rsqrtf(1.0f + (float)g_cnt[i]);
}

// single-block exclusive scan of g_cnt -> g_off (50k elements, 1024 threads)
__global__ void scan_kernel() {
    __shared__ int s[1024];
    int tid = threadIdx.x;
    int carry = 0;
    const int CH = (NN + 1023) / 1024;
    for (int c = 0; c < CH; c++) {
        int i = c * 1024 + tid;
        int v = (i < NN) ? g_cnt[i] : 0;
        s[tid] = v;
        __syncthreads();
#pragma unroll
        for (int off = 1; off < 1024; off <<= 1) {
            int t = (tid >= off) ? s[tid - off] : 0;
            __syncthreads();
            s[tid] += t;
            __syncthreads();
        }
        if (i < NN) g_off[i] = carry + s[tid] - v;  // exclusive
        int tot = s[1023];
        __syncthreads();
        carry += tot;
    }
}

__global__ void fill_kernel(const int* __restrict__ ei) {
    int e = blockIdx.x * 256 + threadIdx.x;
    if (e >= NE) return;
    unsigned src = (unsigned)get_idx(ei, e);
    unsigned dst = (unsigned)get_idx(ei, (long)NE + e);
    if (src >= NN || dst >= NN) return;
    int pos = atomicAdd(&g_cur[dst], 1);
    g_bkt[g_off[dst] + pos] = (int)src;
}

// ---------------- projection GEMM + concat ----------------
// x[:, 0:112] = llm_feat @ proj_W + proj_b ; x[:, 112:128] = struct_emb[type]
// M=50000, N=112, K=640. BM=128, BN=112, BK=32, 256 threads, tile 4x14.
// Register-prefetch double buffering: load tile kt+1 into regs during compute of kt.
__global__ __launch_bounds__(256) void proj_kernel(
    const float* __restrict__ llm, const float* __restrict__ W,
    const float* __restrict__ bias, const float* __restrict__ semb,
    const int* __restrict__ tids)
{
    __shared__ float As[32][133];   // odd stride -> conflict-free transposed stores
    __shared__ float Bs[32][114];

    int tid  = threadIdx.x;
    int m0   = blockIdx.x * 128;
    int kq   = tid & 7;
    int row0 = tid >> 3;
    int colT = tid & 7;

    unsigned long long acc[4][7];
#pragma unroll
    for (int r = 0; r < 4; r++)
#pragma unroll
        for (int j = 0; j < 7; j++) acc[r][j] = 0ull;

    float4 pa4[4];
    float  pb[14];

    // prefetch tile 0
    {
#pragma unroll
        for (int r = 0; r < 4; r++) {
            int gm = m0 + row0 + r * 32;
            pa4[r] = make_float4(0.f, 0.f, 0.f, 0.f);
            if (gm < NN) pa4[r] = *(const float4*)&llm[(long)gm * LDIM + kq * 4];
        }
#pragma unroll
        for (int it = 0; it < 14; it++) {
            int idx = tid + it * 256;
            pb[it] = W[(idx / 112) * POUT + idx % 112];
        }
    }

    const int NT = LDIM / 32;  // 20
    for (int kt = 0; kt < NT; kt++) {
        // store prefetched tile to smem
#pragma unroll
        for (int r = 0; r < 4; r++) {
            int row = row0 + r * 32;
            As[kq * 4 + 0][row] = pa4[r].x;
            As[kq * 4 + 1][row] = pa4[r].y;
            As[kq * 4 + 2][row] = pa4[r].z;
            As[kq * 4 + 3][row] = pa4[r].w;
        }
#pragma unroll
        for (int it = 0; it < 14; it++) {
            int idx = tid + it * 256;
            Bs[idx / 112][idx % 112] = pb[it];
        }
        __syncthreads();

        // prefetch next tile (global loads overlap with compute below)
        if (kt + 1 < NT) {
            int k0 = (kt + 1) * 32;
#pragma unroll
            for (int r = 0; r < 4; r++) {
                int gm = m0 + row0 + r * 32;
                pa4[r] = make_float4(0.f, 0.f, 0.f, 0.f);
                if (gm < NN) pa4[r] = *(const float4*)&llm[(long)gm * LDIM + k0 + kq * 4];
            }
#pragma unroll
            for (int it = 0; it < 14; it++) {
                int idx = tid + it * 256;
                pb[it] = W[(k0 + idx / 112) * POUT + idx % 112];
            }
        }

#pragma unroll 8
        for (int k = 0; k < 32; k++) {
            unsigned long long pa[4];
#pragma unroll
            for (int r = 0; r < 4; r++) pa[r] = pack_dup(As[k][row0 + r * 32]);
            const unsigned long long* bp =
                (const unsigned long long*)&Bs[k][colT * 14];
#pragma unroll
            for (int j = 0; j < 7; j++) {
                unsigned long long bb = bp[j];
#pragma unroll
                for (int r = 0; r < 4; r++) fma2(acc[r][j], pa[r], bb);
            }
        }
        __syncthreads();
    }

    int cb = colT * 14;
    float2 bp2[7];
#pragma unroll
    for (int j = 0; j < 7; j++) bp2[j] = *(const float2*)&bias[cb + 2 * j];

#pragma unroll
    for (int r = 0; r < 4; r++) {
        int row = m0 + row0 + r * 32;
        if (row >= NN) continue;
#pragma unroll
        for (int j = 0; j < 7; j++) {
            float2 u = unpack2(acc[r][j]);
            u.x += bp2[j].x;
            u.y += bp2[j].y;
            *(float2*)&g_x[(long)row * HID + cb + 2 * j] = u;
        }
    }

    // struct-embedding concat: 128 rows x 16 cols
#pragma unroll
    for (int h = 0; h < 2; h++) {
        int row = m0 + h * 64 + (tid >> 2);
        int c4  = (tid & 3) * 4;
        if (row < NN) {
            unsigned t = (unsigned)get_idx(tids, row);
            if (t >= 5) t = 0;
            float4 v = *(const float4*)&semb[t * SDIM + c4];
            *(float4*)&g_x[(long)row * HID + POUT + c4] = v;
        }
    }
}

// ---------------- GCN layer GEMM: xws = (x @ W) * dis[row] ----------------
// M=50000, N=128, K=128. BM=128, BN=128, BK=32, 256 threads, tile 4x16.
// Interleaved columns + register-prefetch double buffering.
__global__ __launch_bounds__(256) void gcn_gemm_kernel(const float* __restrict__ W)
{
    __shared__ float As[32][133];
    __shared__ float Bs[32][130];

    int tid  = threadIdx.x;
    int m0   = blockIdx.x * 128;
    int kq   = tid & 7;
    int row0 = tid >> 3;
    int colT = tid & 7;

    unsigned long long acc[4][8];
#pragma unroll
    for (int r = 0; r < 4; r++)
#pragma unroll
        for (int j = 0; j < 8; j++) acc[r][j] = 0ull;

    float4 pa4[4];
    float  pb[16];

    // prefetch tile 0
    {
#pragma unroll
        for (int r = 0; r < 4; r++) {
            int gm = m0 + row0 + r * 32;
            pa4[r] = make_float4(0.f, 0.f, 0.f, 0.f);
            if (gm < NN) pa4[r] = *(const float4*)&g_x[(long)gm * HID + kq * 4];
        }
#pragma unroll
        for (int it = 0; it < 16; it++) {
            int idx = tid + it * 256;
            pb[it] = W[(idx >> 7) * HID + (idx & 127)];
        }
    }

    const int NT = HID / 32;  // 4
    for (int kt = 0; kt < NT; kt++) {
#pragma unroll
        for (int r = 0; r < 4; r++) {
            int row = row0 + r * 32;
            As[kq * 4 + 0][row] = pa4[r].x;
            As[kq * 4 + 1][row] = pa4[r].y;
            As[kq * 4 + 2][row] = pa4[r].z;
            As[kq * 4 + 3][row] = pa4[r].w;
        }
#pragma unroll
        for (int it = 0; it < 16; it++) {
            int idx = tid + it * 256;
            Bs[idx >> 7][idx & 127] = pb[it];
        }
        __syncthreads();

        if (kt + 1 < NT) {
            int k0 = (kt + 1) * 32;
#pragma unroll
            for (int r = 0; r < 4; r++) {
                int gm = m0 + row0 + r * 32;
                pa4[r] = make_float4(0.f, 0.f, 0.f, 0.f);
                if (gm < NN) pa4[r] = *(const float4*)&g_x[(long)gm * HID + k0 + kq * 4];
            }
#pragma unroll
            for (int it = 0; it < 16; it++) {
                int idx = tid + it * 256;
                pb[it] = W[(k0 + (idx >> 7)) * HID + (idx & 127)];
            }
        }

#pragma unroll 8
        for (int k = 0; k < 32; k++) {
            unsigned long long pa[4];
#pragma unroll
            for (int r = 0; r < 4; r++) pa[r] = pack_dup(As[k][row0 + r * 32]);
#pragma unroll
            for (int j = 0; j < 8; j++) {
                unsigned long long bb =
                    *(const unsigned long long*)&Bs[k][colT * 2 + 16 * j];
#pragma unroll
                for (int r = 0; r < 4; r++) fma2(acc[r][j], pa[r], bb);
            }
        }
        __syncthreads();
    }

#pragma unroll
    for (int r = 0; r < 4; r++) {
        int row = m0 + row0 + r * 32;
        if (row >= NN) continue;
        float dr = g_dis[row];          // pre-scale by dis[row]
#pragma unroll
        for (int j = 0; j < 8; j++) {
            float2 u = unpack2(acc[r][j]);
            u.x *= dr; u.y *= dr;
            *(float2*)&g_xws[(long)row * HID + colT * 2 + 16 * j] = u;
        }
    }
}

// ---------------- CSR gather ----------------
// agg = dis[w] * ( sum_{src->w} xws[src] + xws[w] ) + b ; x[w] += relu(agg)
// One warp per node, lane owns 4 consecutive features.
// LAST=1: fuse LayerNorm and write to out instead of g_x.
template<int LAST>
__global__ __launch_bounds__(256) void gather_kernel(
    const float* __restrict__ bias, const float* __restrict__ lng,
    const float* __restrict__ lnb, float* __restrict__ out)
{
    int w = (blockIdx.x * 256 + threadIdx.x) >> 5;
    if (w >= NN) return;
    int lane = threadIdx.x & 31;

    int   deg = g_cnt[w];
    int   off = g_off[w];
    float dw  = g_dis[w];

    // start from self-loop term: xws[w]
    float4 acc = *(const float4*)&g_xws[(long)w * HID + lane * 4];

    for (int base = 0; base < deg; base += 32) {
        int e   = base + lane;
        int src = (e < deg) ? __ldg(&g_bkt[off + e]) : 0;
        int n   = min(32, deg - base);
#pragma unroll 4
        for (int j = 0; j < n; j++) {
            int s = __shfl_sync(0xFFFFFFFFu, src, j);
            float4 v = *(const float4*)&g_xws[(long)s * HID + lane * 4];
            acc.x += v.x;
            acc.y += v.y;
            acc.z += v.z;
            acc.w += v.w;
        }
    }

    // scale by dis[w], add bias
    float4 b4 = *(const float4*)&bias[lane * 4];
    acc.x = fmaf(acc.x, dw, b4.x);
    acc.y = fmaf(acc.y, dw, b4.y);
    acc.z = fmaf(acc.z, dw, b4.z);
    acc.w = fmaf(acc.w, dw, b4.w);

    // residual + relu
    float4 x = *(const float4*)&g_x[(long)w * HID + lane * 4];
    x.x += fmaxf(acc.x, 0.f);
    x.y += fmaxf(acc.y, 0.f);
    x.z += fmaxf(acc.z, 0.f);
    x.w += fmaxf(acc.w, 0.f);

    if (!LAST) {
        *(float4*)&g_x[(long)w * HID + lane * 4] = x;
    } else {
        // fused LayerNorm
        float s = x.x + x.y + x.z + x.w;
#pragma unroll
        for (int o = 16; o; o >>= 1) s += __shfl_xor_sync(0xFFFFFFFFu, s, o);
        float mean = s * (1.0f / HID);
        float dx = x.x - mean, dy = x.y - mean, dz = x.z - mean, dq = x.w - mean;
        float vs = dx * dx + dy * dy + dz * dz + dq * dq;
#pragma unroll
        for (int o = 16; o; o >>= 1) vs += __shfl_xor_sync(0xFFFFFFFFu, vs, o);
        float inv = rsqrtf(vs * (1.0f / HID) + LN_EPS);
        float4 gg = *(const float4*)&lng[lane * 4];
        float4 bb = *(const float4*)&lnb[lane * 4];
        float4 o4;
        o4.x = dx * inv * gg.x + bb.x;
        o4.y = dy * inv * gg.y + bb.y;
        o4.z = dz * inv * gg.z + bb.z;
        o4.w = dq * inv * gg.w + bb.w;
        *(float4*)&out[(long)w * HID + lane * 4] = o4;
    }
}

// ---------------- launch ----------------
extern "C" void kernel_launch(void* const* d_in, const int* in_sizes, int n_in,
                              void* d_out, int out_size) {
    const float* llm   = (const float*)d_in[0];
    const int*   tids  = (const int*)d_in[1];   // int32 or int64 (detected)
    const int*   ei    = (const int*)d_in[2];   // int32 or int64 (detected)
    const float* projW = (const float*)d_in[3];
    const float* projb = (const float*)d_in[4];
    const float* semb  = (const float*)d_in[5];
    const float* gcnW  = (const float*)d_in[6];
    const float* gcnb  = (const float*)d_in[7];
    const float* lng   = (const float*)d_in[8];
    const float* lnb   = (const float*)d_in[9];
    float*       out   = (float*)d_out;

    (void)in_sizes; (void)n_in; (void)out_size;

    // dtype sniff + CSR build + degree normalization
    detect_kernel<<<1, 64>>>(ei);
    zero_cnt_kernel<<<(NN + 255) / 256, 256>>>();
    count_deg_kernel<<<(NE + 255) / 256, 256>>>(ei);
    dis_kernel<<<(NN + 255) / 256, 256>>>();
    scan_kernel<<<1, 1024>>>();
    fill_kernel<<<(NE + 255) / 256, 256>>>(ei);

    // features
    proj_kernel<<<(NN + 127) / 128, 256>>>(llm, projW, projb, semb, tids);

    const int GATHER_GRID = (NN * 32 + 255) / 256;

    // layer 0
    gcn_gemm_kernel<<<(NN + 127) / 128, 256>>>(gcnW);
    gather_kernel<0><<<GATHER_GRID, 256>>>(gcnb, lng, lnb, out);

    // layer 1 (fused LayerNorm -> out)
    gcn_gemm_kernel<<<(NN + 127) / 128, 256>>>(gcnW + HID * HID);
    gather_kernel<1><<<GATHER_GRID, 256>>>(gcnb + HID, lng, lnb, out);
}

// round 8
// speedup vs baseline: 1.0440x; 1.0440x over previous
#include <cuda_runtime.h>

#define NN   50000
#define NE   600000
#define LDIM 640
#define HID  128
#define SDIM 16
#define POUT 112
#define LN_EPS 1e-5f
#define NB   49      // scan blocks: 49 * 1024 >= NN

// ---------------- scratch (no allocations allowed) ----------------
__device__ float g_x  [NN * HID];
__device__ float g_xws[NN * HID];   // xw * dis[row]  (pre-scaled)
__device__ float g_dis[NN];
__device__ int   g_cnt[NN];
__device__ int   g_off[NN];
__device__ int   g_cur[NN];
__device__ int   g_bkt[NE];
__device__ int   g_bsum[NB];
__device__ int   g_is64;            // 1 if index inputs are int64, 0 if int32

// ---------------- index access (dtype-agnostic) ----------------
__device__ __forceinline__ int get_idx(const int* __restrict__ p, long i) {
    return g_is64 ? p[2 * i] : p[i];
}

// Detect layout: odd 32-bit words of an int64 array of small nonnegative
// values are all zero; for int32 random values in [0,NN) they are ~never all zero.
__global__ void detect_kernel(const int* __restrict__ ei32) {
    __shared__ int nz;
    if (threadIdx.x == 0) nz = 0;
    __syncthreads();
    int v = ei32[2 * threadIdx.x + 1];   // first 64 odd words
    if (v != 0) atomicAdd(&nz, 1);
    __syncthreads();
    if (threadIdx.x == 0) g_is64 = (nz == 0) ? 1 : 0;
}

// ---------------- f32x2 packed-FMA helpers ----------------
__device__ __forceinline__ unsigned long long pack_dup(float x) {
    unsigned long long r;
    asm("mov.b64 %0, {%1, %1};" : "=l"(r) : "f"(x));
    return r;
}
__device__ __forceinline__ void fma2(unsigned long long& d, unsigned long long a,
                                     unsigned long long b) {
    asm("fma.rn.f32x2 %0, %1, %2, %0;" : "+l"(d) : "l"(a), "l"(b));
}
__device__ __forceinline__ float2 unpack2(unsigned long long v) {
    float2 f;
    asm("mov.b64 {%0, %1}, %2;" : "=f"(f.x), "=f"(f.y) : "l"(v));
    return f;
}

// ---------------- degree / CSR build ----------------
__global__ void zero_cnt_kernel() {
    int i = blockIdx.x * 256 + threadIdx.x;
    if (i < NN) { g_cnt[i] = 0; g_cur[i] = 0; }
}

__global__ void count_deg_kernel(const int* __restrict__ ei) {
    int e = blockIdx.x * 256 + threadIdx.x;
    if (e >= NE) return;
    unsigned dst = (unsigned)get_idx(ei, (long)NE + e);
    if (dst < NN) atomicAdd(&g_cnt[dst], 1);
}

// parallel scan, stage 1: per-block exclusive scan of g_cnt -> g_off (local),
// block totals -> g_bsum. grid NB, block 1024.
__global__ void scan_block_kernel() {
    __shared__ int ws[32];
    int t = threadIdx.x, lane = t & 31, wid = t >> 5;
    int i = blockIdx.x * 1024 + t;
    int v = (i < NN) ? g_cnt[i] : 0;
    int x = v;
#pragma unroll
    for (int o = 1; o < 32; o <<= 1) {
        int tt = __shfl_up_sync(0xFFFFFFFFu, x, o);
        if (lane >= o) x += tt;
    }
    if (lane == 31) ws[wid] = x;
    __syncthreads();
    if (wid == 0) {
        int y = ws[lane];
#pragma unroll
        for (int o = 1; o < 32; o <<= 1) {
            int tt = __shfl_up_sync(0xFFFFFFFFu, y, o);
            if (lane >= o) y += tt;
        }
        ws[lane] = y;
    }
    __syncthreads();
    int add = wid ? ws[wid - 1] : 0;
    if (i < NN) g_off[i] = add + x - v;           // block-local exclusive
    if (t == 1023) g_bsum[blockIdx.x] = add + x;  // block total
}

// stage 2: exclusive scan of NB block totals. 1 block, 64 threads.
__global__ void scan_top_kernel() {
    __shared__ int ws[2];
    int t = threadIdx.x, lane = t & 31, wid = t >> 5;
    int v = (t < NB) ? g_bsum[t] : 0;
    int x = v;
#pragma unroll
    for (int o = 1; o < 32; o <<= 1) {
        int tt = __shfl_up_sync(0xFFFFFFFFu, x, o);
        if (lane >= o) x += tt;
    }
    if (lane == 31) ws[wid] = x;
    __syncthreads();
    int add = (wid == 1) ? ws[0] : 0;
    if (t < NB) g_bsum[t] = add + x - v;          // exclusive
}

// stage 3: add block offsets; also compute dis = rsqrt(1+deg).
__global__ void scan_add_dis_kernel() {
    int i = blockIdx.x * 256 + threadIdx.x;
    if (i >= NN) return;
    g_off[i] += g_bsum[i >> 10];
    g_dis[i] = rsqrtf(1.0f + (float)g_cnt[i]);
}

__global__ void fill_kernel(const int* __restrict__ ei) {
    int e = blockIdx.x * 256 + threadIdx.x;
    if (e >= NE) return;
    unsigned src = (unsigned)get_idx(ei, e);
    unsigned dst = (unsigned)get_idx(ei, (long)NE + e);
    if (src >= NN || dst >= NN) return;
    int pos = atomicAdd(&g_cur[dst], 1);
    g_bkt[g_off[dst] + pos] = (int)src;
}

// ---------------- projection GEMM + concat ----------------
// x[:, 0:112] = llm_feat @ proj_W + proj_b ; x[:, 112:128] = struct_emb[type]
// M=50000, N=112, K=640. BM=128, BN=112, BK=32, 256 threads, tile 4x14.
// A tile stored pre-duplicated as f32x2 pairs (kills per-k pack MOVs).
__global__ __launch_bounds__(256) void proj_kernel(
    const float* __restrict__ llm, const float* __restrict__ W,
    const float* __restrict__ bias, const float* __restrict__ semb,
    const int* __restrict__ tids)
{
    __shared__ unsigned long long As2[32][129];  // P=129 (==1 mod 4): conflict-free STS.64/LDS.64
    __shared__ float Bs[32][114];

    int tid  = threadIdx.x;
    int m0   = blockIdx.x * 128;
    int kq   = tid & 7;
    int row0 = tid >> 3;
    int colT = tid & 7;

    unsigned long long acc[4][7];
#pragma unroll
    for (int r = 0; r < 4; r++)
#pragma unroll
        for (int j = 0; j < 7; j++) acc[r][j] = 0ull;

    float4 pa4[4];
    float  pb[14];

    // prefetch tile 0
    {
#pragma unroll
        for (int r = 0; r < 4; r++) {
            int gm = m0 + row0 + r * 32;
            pa4[r] = make_float4(0.f, 0.f, 0.f, 0.f);
            if (gm < NN) pa4[r] = *(const float4*)&llm[(long)gm * LDIM + kq * 4];
        }
#pragma unroll
        for (int it = 0; it < 14; it++) {
            int idx = tid + it * 256;
            pb[it] = W[(idx / 112) * POUT + idx % 112];
        }
    }

    const int NT = LDIM / 32;  // 20
    for (int kt = 0; kt < NT; kt++) {
        // store prefetched tile to smem (A duplicated into f32x2 pairs)
#pragma unroll
        for (int r = 0; r < 4; r++) {
            int row = row0 + r * 32;
            As2[kq * 4 + 0][row] = pack_dup(pa4[r].x);
            As2[kq * 4 + 1][row] = pack_dup(pa4[r].y);
            As2[kq * 4 + 2][row] = pack_dup(pa4[r].z);
            As2[kq * 4 + 3][row] = pack_dup(pa4[r].w);
        }
#pragma unroll
        for (int it = 0; it < 14; it++) {
            int idx = tid + it * 256;
            Bs[idx / 112][idx % 112] = pb[it];
        }
        __syncthreads();

        // prefetch next tile (global loads overlap with compute below)
        if (kt + 1 < NT) {
            int k0 = (kt + 1) * 32;
#pragma unroll
            for (int r = 0; r < 4; r++) {
                int gm = m0 + row0 + r * 32;
                pa4[r] = make_float4(0.f, 0.f, 0.f, 0.f);
                if (gm < NN) pa4[r] = *(const float4*)&llm[(long)gm * LDIM + k0 + kq * 4];
            }
#pragma unroll
            for (int it = 0; it < 14; it++) {
                int idx = tid + it * 256;
                pb[it] = W[(k0 + idx / 112) * POUT + idx % 112];
            }
        }

#pragma unroll 8
        for (int k = 0; k < 32; k++) {
            unsigned long long pa[4];
#pragma unroll
            for (int r = 0; r < 4; r++) pa[r] = As2[k][row0 + r * 32];
            const unsigned long long* bp =
                (const unsigned long long*)&Bs[k][colT * 14];
#pragma unroll
            for (int j = 0; j < 7; j++) {
                unsigned long long bb = bp[j];
#pragma unroll
                for (int r = 0; r < 4; r++) fma2(acc[r][j], pa[r], bb);
            }
        }
        __syncthreads();
    }

    int cb = colT * 14;
    float2 bp2[7];
#pragma unroll
    for (int j = 0; j < 7; j++) bp2[j] = *(const float2*)&bias[cb + 2 * j];

#pragma unroll
    for (int r = 0; r < 4; r++) {
        int row = m0 + row0 + r * 32;
        if (row >= NN) continue;
#pragma unroll
        for (int j = 0; j < 7; j++) {
            float2 u = unpack2(acc[r][j]);
            u.x += bp2[j].x;
            u.y += bp2[j].y;
            *(float2*)&g_x[(long)row * HID + cb + 2 * j] = u;
        }
    }

    // struct-embedding concat: 128 rows x 16 cols
#pragma unroll
    for (int h = 0; h < 2; h++) {
        int row = m0 + h * 64 + (tid >> 2);
        int c4  = (tid & 3) * 4;
        if (row < NN) {
            unsigned t = (unsigned)get_idx(tids, row);
            if (t >= 5) t = 0;
            float4 v = *(const float4*)&semb[t * SDIM + c4];
            *(float4*)&g_x[(long)row * HID + POUT + c4] = v;
        }
    }
}

// ---------------- GCN layer GEMM: xws = (x @ W) * dis[row] ----------------
// M=50000, N=128, K=128. BM=128, BN=128, BK=32, 256 threads, tile 4x16.
// Interleaved columns {2*colT + 16*j} (conflict-free); A pre-duplicated.
__global__ __launch_bounds__(256) void gcn_gemm_kernel(const float* __restrict__ W)
{
    __shared__ unsigned long long As2[32][129];
    __shared__ float Bs[32][130];

    int tid  = threadIdx.x;
    int m0   = blockIdx.x * 128;
    int kq   = tid & 7;
    int row0 = tid >> 3;
    int colT = tid & 7;

    unsigned long long acc[4][8];
#pragma unroll
    for (int r = 0; r < 4; r++)
#pragma unroll
        for (int j = 0; j < 8; j++) acc[r][j] = 0ull;

    float4 pa4[4];
    float  pb[16];

    // prefetch tile 0
    {
#pragma unroll
        for (int r = 0; r < 4; r++) {
            int gm = m0 + row0 + r * 32;
            pa4[r] = make_float4(0.f, 0.f, 0.f, 0.f);
            if (gm < NN) pa4[r] = *(const float4*)&g_x[(long)gm * HID + kq * 4];
        }
#pragma unroll
        for (int it = 0; it < 16; it++) {
            int idx = tid + it * 256;
            pb[it] = W[(idx >> 7) * HID + (idx & 127)];
        }
    }

    const int NT = HID / 32;  // 4
    for (int kt = 0; kt < NT; kt++) {
#pragma unroll
        for (int r = 0; r < 4; r++) {
            int row = row0 + r * 32;
            As2[kq * 4 + 0][row] = pack_dup(pa4[r].x);
            As2[kq * 4 + 1][row] = pack_dup(pa4[r].y);
            As2[kq * 4 + 2][row] = pack_dup(pa4[r].z);
            As2[kq * 4 + 3][row] = pack_dup(pa4[r].w);
        }
#pragma unroll
        for (int it = 0; it < 16; it++) {
            int idx = tid + it * 256;
            Bs[idx >> 7][idx & 127] = pb[it];
        }
        __syncthreads();

        if (kt + 1 < NT) {
            int k0 = (kt + 1) * 32;
#pragma unroll
            for (int r = 0; r < 4; r++) {
                int gm = m0 + row0 + r * 32;
                pa4[r] = make_float4(0.f, 0.f, 0.f, 0.f);
                if (gm < NN) pa4[r] = *(const float4*)&g_x[(long)gm * HID + k0 + kq * 4];
            }
#pragma unroll
            for (int it = 0; it < 16; it++) {
                int idx = tid + it * 256;
                pb[it] = W[(k0 + (idx >> 7)) * HID + (idx & 127)];
            }
        }

#pragma unroll 8
        for (int k = 0; k < 32; k++) {
            unsigned long long pa[4];
#pragma unroll
            for (int r = 0; r < 4; r++) pa[r] = As2[k][row0 + r * 32];
#pragma unroll
            for (int j = 0; j < 8; j++) {
                unsigned long long bb =
                    *(const unsigned long long*)&Bs[k][colT * 2 + 16 * j];
#pragma unroll
                for (int r = 0; r < 4; r++) fma2(acc[r][j], pa[r], bb);
            }
        }
        __syncthreads();
    }

#pragma unroll
    for (int r = 0; r < 4; r++) {
        int row = m0 + row0 + r * 32;
        if (row >= NN) continue;
        float dr = g_dis[row];          // pre-scale by dis[row]
#pragma unroll
        for (int j = 0; j < 8; j++) {
            float2 u = unpack2(acc[r][j]);
            u.x *= dr; u.y *= dr;
            *(float2*)&g_xws[(long)row * HID + colT * 2 + 16 * j] = u;
        }
    }
}

// ---------------- CSR gather ----------------
// agg = dis[w] * ( sum_{src->w} xws[src] + xws[w] ) + b ; x[w] += relu(agg)
// One warp per node, lane owns 4 consecutive features.
// LAST=1: fuse LayerNorm and write to out instead of g_x.
template<int LAST>
__global__ __launch_bounds__(256) void gather_kernel(
    const float* __restrict__ bias, const float* __restrict__ lng,
    const float* __restrict__ lnb, float* __restrict__ out)
{
    int w = (blockIdx.x * 256 + threadIdx.x) >> 5;
    if (w >= NN) return;
    int lane = threadIdx.x & 31;

    int   deg = g_cnt[w];
    int   off = g_off[w];
    float dw  = g_dis[w];

    // start from self-loop term: xws[w]
    float4 acc = *(const float4*)&g_xws[(long)w * HID + lane * 4];

    for (int base = 0; base < deg; base += 32) {
        int e   = base + lane;
        int src = (e < deg) ? __ldg(&g_bkt[off + e]) : 0;
        int n   = min(32, deg - base);
#pragma unroll 4
        for (int j = 0; j < n; j++) {
            int s = __shfl_sync(0xFFFFFFFFu, src, j);
            float4 v = *(const float4*)&g_xws[(long)s * HID + lane * 4];
            acc.x += v.x;
            acc.y += v.y;
            acc.z += v.z;
            acc.w += v.w;
        }
    }

    // scale by dis[w], add bias
    float4 b4 = *(const float4*)&bias[lane * 4];
    acc.x = fmaf(acc.x, dw, b4.x);
    acc.y = fmaf(acc.y, dw, b4.y);
    acc.z = fmaf(acc.z, dw, b4.z);
    acc.w = fmaf(acc.w, dw, b4.w);

    // residual + relu
    float4 x = *(const float4*)&g_x[(long)w * HID + lane * 4];
    x.x += fmaxf(acc.x, 0.f);
    x.y += fmaxf(acc.y, 0.f);
    x.z += fmaxf(acc.z, 0.f);
    x.w += fmaxf(acc.w, 0.f);

    if (!LAST) {
        *(float4*)&g_x[(long)w * HID + lane * 4] = x;
    } else {
        // fused LayerNorm
        float s = x.x + x.y + x.z + x.w;
#pragma unroll
        for (int o = 16; o; o >>= 1) s += __shfl_xor_sync(0xFFFFFFFFu, s, o);
        float mean = s * (1.0f / HID);
        float dx = x.x - mean, dy = x.y - mean, dz = x.z - mean, dq = x.w - mean;
        float vs = dx * dx + dy * dy + dz * dz + dq * dq;
#pragma unroll
        for (int o = 16; o; o >>= 1) vs += __shfl_xor_sync(0xFFFFFFFFu, vs, o);
        float inv = rsqrtf(vs * (1.0f / HID) + LN_EPS);
        float4 gg = *(const float4*)&lng[lane * 4];
        float4 bb = *(const float4*)&lnb[lane * 4];
        float4 o4;
        o4.x = dx * inv * gg.x + bb.x;
        o4.y = dy * inv * gg.y + bb.y;
        o4.z = dz * inv * gg.z + bb.z;
        o4.w = dq * inv * gg.w + bb.w;
        *(float4*)&out[(long)w * HID + lane * 4] = o4;
    }
}

// ---------------- launch ----------------
extern "C" void kernel_launch(void* const* d_in, const int* in_sizes, int n_in,
                              void* d_out, int out_size) {
    const float* llm   = (const float*)d_in[0];
    const int*   tids  = (const int*)d_in[1];   // int32 or int64 (detected)
    const int*   ei    = (const int*)d_in[2];   // int32 or int64 (detected)
    const float* projW = (const float*)d_in[3];
    const float* projb = (const float*)d_in[4];
    const float* semb  = (const float*)d_in[5];
    const float* gcnW  = (const float*)d_in[6];
    const float* gcnb  = (const float*)d_in[7];
    const float* lng   = (const float*)d_in[8];
    const float* lnb   = (const float*)d_in[9];
    float*       out   = (float*)d_out;

    (void)in_sizes; (void)n_in; (void)out_size;

    // dtype sniff + CSR build + degree normalization
    detect_kernel<<<1, 64>>>(ei);
    zero_cnt_kernel<<<(NN + 255) / 256, 256>>>();
    count_deg_kernel<<<(NE + 255) / 256, 256>>>(ei);
    scan_block_kernel<<<NB, 1024>>>();
    scan_top_kernel<<<1, 64>>>();
    scan_add_dis_kernel<<<(NN + 255) / 256, 256>>>();
    fill_kernel<<<(NE + 255) / 256, 256>>>(ei);

    // features
    proj_kernel<<<(NN + 127) / 128, 256>>>(llm, projW, projb, semb, tids);

    const int GATHER_GRID = (NN * 32 + 255) / 256;

    // layer 0
    gcn_gemm_kernel<<<(NN + 127) / 128, 256>>>(gcnW);
    gather_kernel<0><<<GATHER_GRID, 256>>>(gcnb, lng, lnb, out);

    // layer 1 (fused LayerNorm -> out)
    gcn_gemm_kernel<<<(NN + 127) / 128, 256>>>(gcnW + HID * HID);
    gather_kernel<1><<<GATHER_GRID, 256>>>(gcnb + HID, lng, lnb, out);
}